// round 2
// baseline (speedup 1.0000x reference)
#include <cuda_runtime.h>
#include <math.h>

// Shape-specialized for this problem instance.
#define HF 37
#define WF 50
#define CH 512
#define C4 (CH / 4)          // 128 float4 per pixel
#define POOL 7
#define CELLS (POOL * POOL)  // 49

__global__ __launch_bounds__(C4)
void roipool_kernel(const float4* __restrict__ feat,   // [HF*WF, C4]
                    const float*  __restrict__ rois,   // [N,4] x1,y1,x2,y2
                    const int*    __restrict__ im,     // [2] (h, w)
                    float4* __restrict__ out)          // [N*49, C4]
{
    const int blk  = blockIdx.x;
    const int roi  = blk / CELLS;
    const int cell = blk - roi * CELLS;
    const int py   = cell / POOL;
    const int px   = cell - py * POOL;
    const int tid  = threadIdx.x;

    const float hinv = 1.0f / (float)__ldg(&im[0]);
    const float winv = 1.0f / (float)__ldg(&im[1]);

    const float bx1 = __ldg(&rois[roi * 4 + 0]) * winv;
    const float by1 = __ldg(&rois[roi * 4 + 1]) * hinv;
    const float bx2 = __ldg(&rois[roi * 4 + 2]) * winv;
    const float by2 = __ldg(&rois[roi * 4 + 3]) * hinv;

    const float inv13 = 1.0f / 13.0f;   // SAMP-1 = 13, linspace endpoints

    // Per-block (warp-uniform) corner descriptors for the 2 y and 2 x samples.
    int   y0i[2], y1i[2], x0i[2], x1i[2];
    float wyv[2], wxv[2];

    #pragma unroll
    for (int s = 0; s < 2; ++s) {
        const float ty = (float)(2 * py + s) * inv13;
        float y = (by1 + (by2 - by1) * ty) * (float)(HF - 1);
        y = fminf(fmaxf(y, 0.0f), (float)(HF - 1));
        const float y0f = floorf(y);
        y0i[s] = (int)y0f;
        wyv[s] = y - y0f;
        y1i[s] = min(y0i[s] + 1, HF - 1);

        const float tx = (float)(2 * px + s) * inv13;
        float x = (bx1 + (bx2 - bx1) * tx) * (float)(WF - 1);
        x = fminf(fmaxf(x, 0.0f), (float)(WF - 1));
        const float x0f = floorf(x);
        x0i[s] = (int)x0f;
        wxv[s] = x - x0f;
        x1i[s] = min(x0i[s] + 1, WF - 1);
    }

    // Front-batch all 16 loads (4 corners x 4 samples) for max MLP.
    float4 va[2][2], vb[2][2], vc[2][2], vd[2][2];
    #pragma unroll
    for (int sy = 0; sy < 2; ++sy) {
        #pragma unroll
        for (int sx = 0; sx < 2; ++sx) {
            va[sy][sx] = __ldg(&feat[(y0i[sy] * WF + x0i[sx]) * C4 + tid]);
            vb[sy][sx] = __ldg(&feat[(y0i[sy] * WF + x1i[sx]) * C4 + tid]);
            vc[sy][sx] = __ldg(&feat[(y1i[sy] * WF + x0i[sx]) * C4 + tid]);
            vd[sy][sx] = __ldg(&feat[(y1i[sy] * WF + x1i[sx]) * C4 + tid]);
        }
    }

    float4 acc = make_float4(-INFINITY, -INFINITY, -INFINITY, -INFINITY);

    #pragma unroll
    for (int sy = 0; sy < 2; ++sy) {
        #pragma unroll
        for (int sx = 0; sx < 2; ++sx) {
            const float wy = wyv[sy];
            const float wx = wxv[sx];
            const float w00 = (1.0f - wy) * (1.0f - wx);
            const float w01 = (1.0f - wy) * wx;
            const float w10 = wy * (1.0f - wx);
            const float w11 = wy * wx;

            const float4 a = va[sy][sx];
            const float4 b = vb[sy][sx];
            const float4 c = vc[sy][sx];
            const float4 d = vd[sy][sx];

            float4 v;
            v.x = a.x * w00 + b.x * w01 + c.x * w10 + d.x * w11;
            v.y = a.y * w00 + b.y * w01 + c.y * w10 + d.y * w11;
            v.z = a.z * w00 + b.z * w01 + c.z * w10 + d.z * w11;
            v.w = a.w * w00 + b.w * w01 + c.w * w10 + d.w * w11;

            acc.x = fmaxf(acc.x, v.x);
            acc.y = fmaxf(acc.y, v.y);
            acc.z = fmaxf(acc.z, v.z);
            acc.w = fmaxf(acc.w, v.w);
        }
    }

    out[(size_t)blk * C4 + tid] = acc;
}

extern "C" void kernel_launch(void* const* d_in, const int* in_sizes, int n_in,
                              void* d_out, int out_size) {
    const float4* feat = (const float4*)d_in[0];
    const float*  rois = (const float*)d_in[1];
    const int*    im   = (const int*)d_in[2];
    float4*       out  = (float4*)d_out;

    const int n = in_sizes[1] / 4;   // number of rois
    roipool_kernel<<<n * CELLS, C4>>>(feat, rois, im, out);
}

// round 5
// speedup vs baseline: 1.0772x; 1.0772x over previous
#include <cuda_runtime.h>
#include <math.h>

// Shape-specialized for this problem instance.
#define HF 37
#define WF 50
#define CH 512
#define C4 (CH / 4)          // 128 float4 per pixel
#define POOL 7
#define CELLS (POOL * POOL)  // 49

__device__ __forceinline__ void bmax(float4& acc,
                                     const float4 a, const float4 b,
                                     const float4 c, const float4 d,
                                     const float wy, const float wx) {
    const float w00 = (1.0f - wy) * (1.0f - wx);
    const float w01 = (1.0f - wy) * wx;
    const float w10 = wy * (1.0f - wx);
    const float w11 = wy * wx;
    acc.x = fmaxf(acc.x, a.x * w00 + b.x * w01 + c.x * w10 + d.x * w11);
    acc.y = fmaxf(acc.y, a.y * w00 + b.y * w01 + c.y * w10 + d.y * w11);
    acc.z = fmaxf(acc.z, a.z * w00 + b.z * w01 + c.z * w10 + d.z * w11);
    acc.w = fmaxf(acc.w, a.w * w00 + b.w * w01 + c.w * w10 + d.w * w11);
}

// Fast path: the 4 samples' corner pixels form a (2+DY)x(2+DX) rectangle
// starting at (R0, C0). Load each distinct pixel exactly once.
// Sample sy uses rows {sy*DY, sy*DY+1}; sample sx uses cols {sx*DX, sx*DX+1}.
// Boundary clamping is folded into the load indices: register (i,j) holds
// row min(R0+i,HF-1), col min(C0+j,WF-1), which matches the clipped y1/x1.
template<int DY, int DX>
__device__ __forceinline__ float4 cell_fast(const float4* __restrict__ feat,
                                            const int R0, const int C0,
                                            const float* wyv, const float* wxv,
                                            const int tid) {
    float4 P[2 + DY][2 + DX];
    #pragma unroll
    for (int i = 0; i < 2 + DY; ++i) {
        const int r = min(R0 + i, HF - 1);
        #pragma unroll
        for (int j = 0; j < 2 + DX; ++j) {
            const int c = min(C0 + j, WF - 1);
            P[i][j] = __ldg(&feat[(r * WF + c) * C4 + tid]);
        }
    }
    float4 acc = make_float4(-INFINITY, -INFINITY, -INFINITY, -INFINITY);
    #pragma unroll
    for (int sy = 0; sy < 2; ++sy) {
        #pragma unroll
        for (int sx = 0; sx < 2; ++sx) {
            bmax(acc,
                 P[sy * DY    ][sx * DX    ],
                 P[sy * DY    ][sx * DX + 1],
                 P[sy * DY + 1][sx * DX    ],
                 P[sy * DY + 1][sx * DX + 1],
                 wyv[sy], wxv[sx]);
        }
    }
    return acc;
}

__global__ __launch_bounds__(C4)
void roipool_kernel(const float4* __restrict__ feat,   // [HF*WF, C4]
                    const float*  __restrict__ rois,   // [N,4] x1,y1,x2,y2
                    const int*    __restrict__ im,     // [2] (h, w)
                    float4* __restrict__ out)          // [N*49, C4]
{
    const int blk  = blockIdx.x;
    const int roi  = blk / CELLS;
    const int cell = blk - roi * CELLS;
    const int py   = cell / POOL;
    const int px   = cell - py * POOL;
    const int tid  = threadIdx.x;

    const float hinv = 1.0f / (float)__ldg(&im[0]);
    const float winv = 1.0f / (float)__ldg(&im[1]);

    const float bx1 = __ldg(&rois[roi * 4 + 0]) * winv;
    const float by1 = __ldg(&rois[roi * 4 + 1]) * hinv;
    const float bx2 = __ldg(&rois[roi * 4 + 2]) * winv;
    const float by2 = __ldg(&rois[roi * 4 + 3]) * hinv;

    const float inv13 = 1.0f / 13.0f;   // SAMP-1 = 13, linspace endpoints

    // Warp-uniform corner descriptors for the 2 y and 2 x samples.
    int   y0i[2], y1i[2], x0i[2], x1i[2];
    float wyv[2], wxv[2];

    #pragma unroll
    for (int s = 0; s < 2; ++s) {
        const float ty = (float)(2 * py + s) * inv13;
        float y = (by1 + (by2 - by1) * ty) * (float)(HF - 1);
        y = fminf(fmaxf(y, 0.0f), (float)(HF - 1));
        const float y0f = floorf(y);
        y0i[s] = (int)y0f;
        wyv[s] = y - y0f;
        y1i[s] = min(y0i[s] + 1, HF - 1);

        const float tx = (float)(2 * px + s) * inv13;
        float x = (bx1 + (bx2 - bx1) * tx) * (float)(WF - 1);
        x = fminf(fmaxf(x, 0.0f), (float)(WF - 1));
        const float x0f = floorf(x);
        x0i[s] = (int)x0f;
        wxv[s] = x - x0f;
        x1i[s] = min(x0i[s] + 1, WF - 1);
    }

    const int dy = y0i[1] - y0i[0];   // >= 0 (samples are monotone)
    const int dx = x0i[1] - x0i[0];

    float4 acc;

    if (dy <= 1 && dx <= 1) {
        // ~93% of cells: shared-corner rectangle, 4/6/9 distinct loads.
        if (dy == 0) {
            if (dx == 0) acc = cell_fast<0, 0>(feat, y0i[0], x0i[0], wyv, wxv, tid);
            else         acc = cell_fast<0, 1>(feat, y0i[0], x0i[0], wyv, wxv, tid);
        } else {
            if (dx == 0) acc = cell_fast<1, 0>(feat, y0i[0], x0i[0], wyv, wxv, tid);
            else         acc = cell_fast<1, 1>(feat, y0i[0], x0i[0], wyv, wxv, tid);
        }
    } else {
        // Rare fallback: fully general 16-load path.
        acc = make_float4(-INFINITY, -INFINITY, -INFINITY, -INFINITY);
        #pragma unroll
        for (int sy = 0; sy < 2; ++sy) {
            #pragma unroll
            for (int sx = 0; sx < 2; ++sx) {
                const float4 a = __ldg(&feat[(y0i[sy] * WF + x0i[sx]) * C4 + tid]);
                const float4 b = __ldg(&feat[(y0i[sy] * WF + x1i[sx]) * C4 + tid]);
                const float4 c = __ldg(&feat[(y1i[sy] * WF + x0i[sx]) * C4 + tid]);
                const float4 d = __ldg(&feat[(y1i[sy] * WF + x1i[sx]) * C4 + tid]);
                bmax(acc, a, b, c, d, wyv[sy], wxv[sx]);
            }
        }
    }

    out[(size_t)blk * C4 + tid] = acc;
}

extern "C" void kernel_launch(void* const* d_in, const int* in_sizes, int n_in,
                              void* d_out, int out_size) {
    const float4* feat = (const float4*)d_in[0];
    const float*  rois = (const float*)d_in[1];
    const int*    im   = (const int*)d_in[2];
    float4*       out  = (float4*)d_out;

    const int n = in_sizes[1] / 4;   // number of rois
    roipool_kernel<<<n * CELLS, C4>>>(feat, rois, im, out);
}

// round 8
// speedup vs baseline: 1.2218x; 1.1343x over previous
#include <cuda_runtime.h>
#include <math.h>

// Shape-specialized for this problem instance.
#define HF 37
#define WF 50
#define CH 512
#define C4 (CH / 4)          // 128 float4 per pixel
#define POOL 7
#define CELLS (POOL * POOL)  // 49
#define SAMP 14
#define NMAX 1024

// Per-(roi, sample) descriptors: {floor_index, bitcast(frac_weight)}.
// Pairs (2p, 2p+1) are contiguous and 16B-aligned -> single int4 load per axis.
__device__ int2 g_ydesc[NMAX * SAMP];
__device__ int2 g_xdesc[NMAX * SAMP];

__global__ void setup_kernel(const float* __restrict__ rois,
                             const int* __restrict__ im, int n) {
    const int i = blockIdx.x * blockDim.x + threadIdx.x;
    if (i >= n * SAMP) return;
    const int roi = i / SAMP;
    const int s   = i - roi * SAMP;

    const float hinv = 1.0f / (float)im[0];
    const float winv = 1.0f / (float)im[1];
    const float t = (float)s * (1.0f / 13.0f);

    const float ny1 = rois[roi * 4 + 1] * hinv;
    const float ny2 = rois[roi * 4 + 3] * hinv;
    float y = (ny1 + (ny2 - ny1) * t) * (float)(HF - 1);
    y = fminf(fmaxf(y, 0.0f), (float)(HF - 1));
    const float y0f = floorf(y);
    g_ydesc[i] = make_int2((int)y0f, __float_as_int(y - y0f));

    const float nx1 = rois[roi * 4 + 0] * winv;
    const float nx2 = rois[roi * 4 + 2] * winv;
    float x = (nx1 + (nx2 - nx1) * t) * (float)(WF - 1);
    x = fminf(fmaxf(x, 0.0f), (float)(WF - 1));
    const float x0f = floorf(x);
    g_xdesc[i] = make_int2((int)x0f, __float_as_int(x - x0f));
}

__device__ __forceinline__ void bmax(float4& acc,
                                     const float4 a, const float4 b,
                                     const float4 c, const float4 d,
                                     const float wy, const float wx) {
    const float w00 = (1.0f - wy) * (1.0f - wx);
    const float w01 = (1.0f - wy) * wx;
    const float w10 = wy * (1.0f - wx);
    const float w11 = wy * wx;
    acc.x = fmaxf(acc.x, a.x * w00 + b.x * w01 + c.x * w10 + d.x * w11);
    acc.y = fmaxf(acc.y, a.y * w00 + b.y * w01 + c.y * w10 + d.y * w11);
    acc.z = fmaxf(acc.z, a.z * w00 + b.z * w01 + c.z * w10 + d.z * w11);
    acc.w = fmaxf(acc.w, a.w * w00 + b.w * w01 + c.w * w10 + d.w * w11);
}

// Fast path: the 4 samples' corner pixels form a (2+DY)x(2+DX) rectangle
// starting at (R0, C0). Load each distinct pixel exactly once; boundary
// clamping is folded into the load indices.
template<int DY, int DX>
__device__ __forceinline__ float4 cell_fast(const float4* __restrict__ fb,
                                            const int R0, const int C0,
                                            const float* wyv, const float* wxv) {
    float4 P[2 + DY][2 + DX];
    #pragma unroll
    for (int i = 0; i < 2 + DY; ++i) {
        const int r = min(R0 + i, HF - 1);
        #pragma unroll
        for (int j = 0; j < 2 + DX; ++j) {
            const int c = min(C0 + j, WF - 1);
            P[i][j] = __ldg(&fb[(r * WF + c) * C4]);
        }
    }
    float4 acc = make_float4(-INFINITY, -INFINITY, -INFINITY, -INFINITY);
    #pragma unroll
    for (int sy = 0; sy < 2; ++sy) {
        #pragma unroll
        for (int sx = 0; sx < 2; ++sx) {
            bmax(acc,
                 P[sy * DY    ][sx * DX    ],
                 P[sy * DY    ][sx * DX + 1],
                 P[sy * DY + 1][sx * DX    ],
                 P[sy * DY + 1][sx * DX + 1],
                 wyv[sy], wxv[sx]);
        }
    }
    return acc;
}

__global__ __launch_bounds__(C4)
void roipool_kernel(const float4* __restrict__ feat,   // [HF*WF, C4]
                    float4* __restrict__ out)          // [N*49, C4]
{
    const int blk  = blockIdx.x;
    const int roi  = blk / CELLS;
    const int cell = blk - roi * CELLS;
    const int py   = cell / POOL;
    const int px   = cell - py * POOL;
    const int tid  = threadIdx.x;

    // Load precomputed sample descriptors (warp-uniform, L1-broadcast).
    const int4 yd = __ldg((const int4*)&g_ydesc[roi * SAMP + 2 * py]);
    const int4 xd = __ldg((const int4*)&g_xdesc[roi * SAMP + 2 * px]);

    const int y0a = yd.x, y0b = yd.z;
    const int x0a = xd.x, x0b = xd.z;
    float wyv[2] = { __int_as_float(yd.y), __int_as_float(yd.w) };
    float wxv[2] = { __int_as_float(xd.y), __int_as_float(xd.w) };

    const int dy = y0b - y0a;   // >= 0 (samples are monotone)
    const int dx = x0b - x0a;

    const float4* fb = feat + tid;   // per-thread channel base

    float4 acc;

    if (dy <= 1 && dx <= 1) {
        // ~93% of cells: shared-corner rectangle, 4/6/9 distinct loads.
        if (dy == 0) {
            if (dx == 0) acc = cell_fast<0, 0>(fb, y0a, x0a, wyv, wxv);
            else         acc = cell_fast<0, 1>(fb, y0a, x0a, wyv, wxv);
        } else {
            if (dx == 0) acc = cell_fast<1, 0>(fb, y0a, x0a, wyv, wxv);
            else         acc = cell_fast<1, 1>(fb, y0a, x0a, wyv, wxv);
        }
    } else {
        // Rare fallback: fully general 16-load path.
        const int y0i[2] = { y0a, y0b };
        const int x0i[2] = { x0a, x0b };
        acc = make_float4(-INFINITY, -INFINITY, -INFINITY, -INFINITY);
        #pragma unroll
        for (int sy = 0; sy < 2; ++sy) {
            const int r0 = y0i[sy];
            const int r1 = min(r0 + 1, HF - 1);
            #pragma unroll
            for (int sx = 0; sx < 2; ++sx) {
                const int c0 = x0i[sx];
                const int c1 = min(c0 + 1, WF - 1);
                const float4 a = __ldg(&fb[(r0 * WF + c0) * C4]);
                const float4 b = __ldg(&fb[(r0 * WF + c1) * C4]);
                const float4 c = __ldg(&fb[(r1 * WF + c0) * C4]);
                const float4 d = __ldg(&fb[(r1 * WF + c1) * C4]);
                bmax(acc, a, b, c, d, wyv[sy], wxv[sx]);
            }
        }
    }

    out[(size_t)blk * C4 + tid] = acc;
}

extern "C" void kernel_launch(void* const* d_in, const int* in_sizes, int n_in,
                              void* d_out, int out_size) {
    const float4* feat = (const float4*)d_in[0];
    const float*  rois = (const float*)d_in[1];
    const int*    im   = (const int*)d_in[2];
    float4*       out  = (float4*)d_out;

    const int n = in_sizes[1] / 4;   // number of rois

    const int setup_threads = n * SAMP;
    setup_kernel<<<(setup_threads + 127) / 128, 128>>>(rois, im, n);
    roipool_kernel<<<n * CELLS, C4>>>(feat, out);
}